// round 1
// baseline (speedup 1.0000x reference)
#include <cuda_runtime.h>
#include <math.h>

#define BATCH 4
#define CIN   128
#define OCH   128
#define HH    256
#define WW    256
#define HWSZ  (HH*WW)

#define EPS_BR  1e-3f
#define EPS_ATT 1e-5f

// scratch (device globals: allocation-free)
__device__ float g_fbuf[(size_t)BATCH*OCH*HWSZ];   // 128 MiB: branch features post-BN (ch 0-63 = a, 64-127 = b)
__device__ float g_att[(size_t)2*BATCH*HWSZ];      // att logits, plane A then plane B

__device__ __forceinline__ float pos_g(int i) {
    // H=W=256 (even): |i - H/2 + 0.5| / (H/2)
    return fabsf((float)i - 127.5f) * (1.0f/128.0f);
}

// ---------------------------------------------------------------------------
// Kernel 1: 3x3 conv (both branches) + BN + fused 1x1 attention logit
// Tile: 8 rows x 64 cols (512 px), 256 threads, 2 px/thread (rows r0, r0+4).
// Loops: oc-chunk(8 x 16oc) outer, ic-chunk(16 x 8ic) inner; x+w staged in smem.
// ---------------------------------------------------------------------------
#define T1H 8
#define T1W 64
#define ICC 8

#define FMA4(A,X,Wv) { (A).x = fmaf((X),(Wv).x,(A).x); (A).y = fmaf((X),(Wv).y,(A).y); \
                       (A).z = fmaf((X),(Wv).z,(A).z); (A).w = fmaf((X),(Wv).w,(A).w); }

__global__ __launch_bounds__(256, 2)
void conv_bn_att_kernel(
    const float* __restrict__ x,
    const float* __restrict__ wa, const float* __restrict__ ba,
    const float* __restrict__ wb, const float* __restrict__ bb,
    const float* __restrict__ ga, const float* __restrict__ bta,
    const float* __restrict__ ma, const float* __restrict__ va,
    const float* __restrict__ gb, const float* __restrict__ btb,
    const float* __restrict__ mb, const float* __restrict__ vb,
    const float* __restrict__ aw_a, const float* __restrict__ ab_a,
    const float* __restrict__ aw_b, const float* __restrict__ ab_b,
    const float* __restrict__ ag_a, const float* __restrict__ abt_a,
    const float* __restrict__ am_a, const float* __restrict__ av_a,
    const float* __restrict__ ag_b, const float* __restrict__ abt_b,
    const float* __restrict__ am_b, const float* __restrict__ av_b)
{
    __shared__ __align__(16) float xs[ICC*10*66];   // 8 ic x (8+2) rows x (64+2) cols
    __shared__ __align__(16) float ws[ICC*9*16];    // [ic*9+tap][16 oc]

    const int tid    = threadIdx.x;
    const int bz     = blockIdx.z;
    const int y_base = blockIdx.y * T1H;
    const int x_base = blockIdx.x * T1W;
    const int r0 = tid >> 6;          // 0..3
    const int c  = tid & 63;          // 0..63
    const int y0 = y_base + r0;
    const int y1 = y0 + 4;
    const int gx = x_base + c;

    float attA0 = 0.f, attA1 = 0.f, attB0 = 0.f, attB1 = 0.f;

    for (int occ = 0; occ < 8; ++occ) {
        float4 acc0[4], acc1[4];
        #pragma unroll
        for (int j = 0; j < 4; ++j) {
            acc0[j] = make_float4(0.f,0.f,0.f,0.f);
            acc1[j] = make_float4(0.f,0.f,0.f,0.f);
        }

        for (int icc = 0; icc < CIN/ICC; ++icc) {
            __syncthreads();
            // stage x slab (8 ic, halo-1)
            for (int i = tid; i < ICC*10*66; i += 256) {
                int ic  = i / 660;
                int rem = i - ic*660;
                int row = rem / 66;
                int col = rem - row*66;
                int gy  = y_base + row - 1;
                int gxx = x_base + col - 1;
                float v = 0.f;
                if ((unsigned)gy < HH && (unsigned)gxx < WW)
                    v = x[(((size_t)bz*CIN + icc*ICC + ic)*HH + gy)*WW + gxx];
                xs[i] = v;
            }
            // stage weights for (occ, icc): layout [ic*9+tap][oc]
            for (int i = tid; i < ICC*9*16; i += 256) {
                int kt  = i >> 4;          // ic*9+tap
                int oc  = i & 15;
                int ic  = kt / 9;
                int tap = kt - ic*9;
                int ocg = occ*16 + oc;
                const float* wbase = (ocg < 64) ? (wa + (size_t)ocg*CIN*9)
                                                : (wb + (size_t)(ocg-64)*CIN*9);
                ws[i] = wbase[(icc*ICC + ic)*9 + tap];
            }
            __syncthreads();

            #pragma unroll 1
            for (int ic = 0; ic < ICC; ++ic) {
                const float*  xb0 = &xs[ic*660 + r0*66 + c];
                const float*  xb1 = xb0 + 4*66;
                const float4* wq  = reinterpret_cast<const float4*>(&ws[ic*9*16]);
                #pragma unroll
                for (int tap = 0; tap < 9; ++tap) {
                    const int dy = tap/3, dx = tap - (tap/3)*3;
                    float xv0 = xb0[dy*66 + dx];
                    float xv1 = xb1[dy*66 + dx];
                    float4 w0 = wq[tap*4+0];
                    float4 w1 = wq[tap*4+1];
                    float4 w2 = wq[tap*4+2];
                    float4 w3 = wq[tap*4+3];
                    FMA4(acc0[0], xv0, w0); FMA4(acc1[0], xv1, w0);
                    FMA4(acc0[1], xv0, w1); FMA4(acc1[1], xv1, w1);
                    FMA4(acc0[2], xv0, w2); FMA4(acc1[2], xv1, w2);
                    FMA4(acc0[3], xv0, w3); FMA4(acc1[3], xv1, w3);
                }
            }
        }

        // epilogue for this 16-oc chunk: BN fold, store f, accumulate attention dot
        #define EPI(K, A0, A1) { \
            int ocg = occ*16 + (K); \
            float s, t, wv; \
            if (ocg < 64) { \
                s  = ga[ocg] * rsqrtf(va[ocg] + EPS_BR); \
                t  = (ba[ocg] - ma[ocg]) * s + bta[ocg]; \
                wv = aw_a[ocg]; \
            } else { \
                int o2 = ocg - 64; \
                s  = gb[o2] * rsqrtf(vb[o2] + EPS_BR); \
                t  = (bb[o2] - mb[o2]) * s + btb[o2]; \
                wv = aw_b[o2]; \
            } \
            float f0 = fmaf((A0), s, t); \
            float f1 = fmaf((A1), s, t); \
            size_t fb = ((size_t)bz*OCH + ocg) * HH; \
            g_fbuf[(fb + y0)*WW + gx] = f0; \
            g_fbuf[(fb + y1)*WW + gx] = f1; \
            if (ocg < 64) { attA0 = fmaf(wv, f0, attA0); attA1 = fmaf(wv, f1, attA1); } \
            else          { attB0 = fmaf(wv, f0, attB0); attB1 = fmaf(wv, f1, attB1); } }

        #pragma unroll
        for (int j = 0; j < 4; ++j) {
            EPI(j*4+0, acc0[j].x, acc1[j].x);
            EPI(j*4+1, acc0[j].y, acc1[j].y);
            EPI(j*4+2, acc0[j].z, acc1[j].z);
            EPI(j*4+3, acc0[j].w, acc1[j].w);
        }
        #undef EPI
    }

    // attention logit epilogue: + w[64]*gh + w[65]*gw + bias, then BN(eps=1e-5)
    float ghv0 = pos_g(y0), ghv1 = pos_g(y1), gwv = pos_g(gx);

    float sA = ag_a[0] * rsqrtf(av_a[0] + EPS_ATT);
    float sB = ag_b[0] * rsqrtf(av_b[0] + EPS_ATT);

    float zA0 = attA0 + aw_a[64]*ghv0 + aw_a[65]*gwv + ab_a[0];
    float zA1 = attA1 + aw_a[64]*ghv1 + aw_a[65]*gwv + ab_a[0];
    float zB0 = attB0 + aw_b[64]*ghv0 + aw_b[65]*gwv + ab_b[0];
    float zB1 = attB1 + aw_b[64]*ghv1 + aw_b[65]*gwv + ab_b[0];

    zA0 = (zA0 - am_a[0])*sA + abt_a[0];
    zA1 = (zA1 - am_a[0])*sA + abt_a[0];
    zB0 = (zB0 - am_b[0])*sB + abt_b[0];
    zB1 = (zB1 - am_b[0])*sB + abt_b[0];

    size_t pa = ((size_t)bz*HH + y0)*WW + gx;
    size_t pb = ((size_t)bz*HH + y1)*WW + gx;
    g_att[pa] = zA0;
    g_att[pb] = zA1;
    g_att[(size_t)BATCH*HWSZ + pa] = zB0;
    g_att[(size_t)BATCH*HWSZ + pb] = zB1;
}

// ---------------------------------------------------------------------------
// Kernel 2: 3x3 attention conv over [att, gh, gw, pr] (zero-padded) + sigmoid,
// then out = f * (map * scale). Tile 8x32, 1 px/thread. DRAM-bound.
// ---------------------------------------------------------------------------
__global__ __launch_bounds__(256)
void map_out_kernel(const float* __restrict__ awA, const float* __restrict__ awB,
                    const float* __restrict__ s1p, const float* __restrict__ s2p,
                    float* __restrict__ out)
{
    __shared__ float aA[10*34], aB[10*34];
    __shared__ float wA[36], wB[36];

    const int tid    = threadIdx.x;
    const int bz     = blockIdx.z;
    const int y_base = blockIdx.y * 8;
    const int x_base = blockIdx.x * 32;

    if (tid < 36) { wA[tid] = awA[tid]; wB[tid] = awB[tid]; }

    for (int i = tid; i < 340; i += 256) {
        int row = i / 34, col = i - row*34;
        int gy = y_base + row - 1, gxx = x_base + col - 1;
        float vA = 0.f, vB = 0.f;
        if ((unsigned)gy < HH && (unsigned)gxx < WW) {
            size_t idx = ((size_t)bz*HH + gy)*WW + gxx;
            vA = g_att[idx];
            vB = g_att[(size_t)BATCH*HWSZ + idx];
        }
        aA[i] = vA; aB[i] = vB;
    }
    __syncthreads();

    const int ty = tid >> 5, tx = tid & 31;
    const int y = y_base + ty, x0 = x_base + tx;

    // polar-r linear-map constants (H=W=256, even)
    const float ghmax = 127.5f/128.f, ghmin = 0.5f/128.f;
    const float prmax = sqrtf(2.f)*ghmax, prmin = sqrtf(2.f)*ghmin;
    const float kk = 2.f/(prmax - prmin);
    const float c0 = 1.f - prmax*kk;

    float sumA = 0.f, sumB = 0.f;
    #pragma unroll
    for (int ky = 0; ky < 3; ++ky) {
        #pragma unroll
        for (int kx = 0; kx < 3; ++kx) {
            int tap = ky*3 + kx;
            int yy = y + ky - 1, xx = x0 + kx - 1;
            float av = aA[(ty+ky)*34 + tx + kx];
            float bv = aB[(ty+ky)*34 + tx + kx];
            sumA = fmaf(wA[tap], av, sumA);
            sumB = fmaf(wB[tap], bv, sumB);
            if ((unsigned)yy < HH && (unsigned)xx < WW) {   // position channels zero-padded OOB
                float ghv = pos_g(yy), gwv = pos_g(xx);
                float prv = fmaf(kk, sqrtf(ghv*ghv + gwv*gwv), c0);
                sumA += wA[9+tap]*ghv + wA[18+tap]*gwv + wA[27+tap]*prv;
                sumB += wB[9+tap]*ghv + wB[18+tap]*gwv + wB[27+tap]*prv;
            }
        }
    }

    float mA = (1.f/(1.f + expf(-sumA))) * s1p[0];
    float mB = (1.f/(1.f + expf(-sumB))) * s2p[0];

    size_t idx = (((size_t)bz*OCH)*HH + y)*WW + x0;
    #pragma unroll 8
    for (int oc = 0; oc < OCH; ++oc) {
        float m = (oc < 64) ? mA : mB;
        out[idx] = g_fbuf[idx] * m;
        idx += (size_t)HWSZ;
    }
}

// ---------------------------------------------------------------------------
extern "C" void kernel_launch(void* const* d_in, const int* in_sizes, int n_in,
                              void* d_out, int out_size)
{
    const float* x     = (const float*)d_in[0];
    const float* wa    = (const float*)d_in[1];
    const float* ba    = (const float*)d_in[2];
    const float* wb    = (const float*)d_in[3];
    const float* bb    = (const float*)d_in[4];
    const float* ga    = (const float*)d_in[5];
    const float* bta   = (const float*)d_in[6];
    const float* ma    = (const float*)d_in[7];
    const float* va    = (const float*)d_in[8];
    const float* gb    = (const float*)d_in[9];
    const float* btb   = (const float*)d_in[10];
    const float* mb    = (const float*)d_in[11];
    const float* vb    = (const float*)d_in[12];
    const float* aw_a  = (const float*)d_in[13];
    const float* ab_a  = (const float*)d_in[14];
    const float* aw_b  = (const float*)d_in[15];
    const float* ab_b  = (const float*)d_in[16];
    const float* ag_a  = (const float*)d_in[17];
    const float* abt_a = (const float*)d_in[18];
    const float* am_a  = (const float*)d_in[19];
    const float* av_a  = (const float*)d_in[20];
    const float* ag_b  = (const float*)d_in[21];
    const float* abt_b = (const float*)d_in[22];
    const float* am_b  = (const float*)d_in[23];
    const float* av_b  = (const float*)d_in[24];
    const float* awnA  = (const float*)d_in[25];
    const float* awnB  = (const float*)d_in[26];
    const float* s1    = (const float*)d_in[27];
    const float* s2    = (const float*)d_in[28];
    float* out = (float*)d_out;

    dim3 g1(WW/T1W, HH/T1H, BATCH);   // (4, 32, 4)
    conv_bn_att_kernel<<<g1, 256>>>(x, wa, ba, wb, bb,
                                    ga, bta, ma, va, gb, btb, mb, vb,
                                    aw_a, ab_a, aw_b, ab_b,
                                    ag_a, abt_a, am_a, av_a,
                                    ag_b, abt_b, am_b, av_b);

    dim3 g2(WW/32, HH/8, BATCH);      // (8, 32, 4)
    map_out_kernel<<<g2, 256>>>(awnA, awnB, s1, s2, out);
}

// round 4
// speedup vs baseline: 1.0374x; 1.0374x over previous
#include <cuda_runtime.h>
#include <math.h>

#define BATCH 4
#define CIN   128
#define OCH   128
#define HH    256
#define WW    256
#define HWSZ  (HH*WW)

#define EPS_BR  1e-3f
#define EPS_ATT 1e-5f

// scratch (device globals: allocation-free)
__device__ float g_fbuf[(size_t)BATCH*OCH*HWSZ];   // branch features post-BN (ch 0-63 = a, 64-127 = b)
__device__ float g_att[(size_t)2*BATCH*HWSZ];      // att logits, plane A then plane B

__device__ __forceinline__ float pos_g(int i) {
    return fabsf((float)i - 127.5f) * (1.0f/128.0f);
}

// ---- packed f32x2 helpers --------------------------------------------------
typedef unsigned long long u64;

__device__ __forceinline__ u64 pack2(float v) {
    u64 r;
    asm("mov.b64 %0, {%1, %1};" : "=l"(r) : "r"(__float_as_uint(v)));
    return r;
}
__device__ __forceinline__ void ffma2(u64 &acc, u64 a, u64 b) {
    asm("fma.rn.f32x2 %0, %1, %2, %0;" : "+l"(acc) : "l"(a), "l"(b));
}
__device__ __forceinline__ float2 unpack2(u64 v) {
    float2 f;
    asm("mov.b64 {%0, %1}, %2;" : "=f"(f.x), "=f"(f.y) : "l"(v));
    return f;
}

// ---------------------------------------------------------------------------
// Kernel 1: 3x3 conv (both branches) + BN + fused 1x1 attention logit.
// Tile: 8 rows x 64 cols, 256 threads, 2 px/thread. FFMA2 mainloop.
// ---------------------------------------------------------------------------
#define T1H 8
#define T1W 64
#define ICC 8

__global__ __launch_bounds__(256, 2)
void conv_bn_att_kernel(
    const float* __restrict__ x,
    const float* __restrict__ wa, const float* __restrict__ ba,
    const float* __restrict__ wb, const float* __restrict__ bb,
    const float* __restrict__ ga, const float* __restrict__ bta,
    const float* __restrict__ ma, const float* __restrict__ va,
    const float* __restrict__ gb, const float* __restrict__ btb,
    const float* __restrict__ mb, const float* __restrict__ vb,
    const float* __restrict__ aw_a, const float* __restrict__ ab_a,
    const float* __restrict__ aw_b, const float* __restrict__ ab_b,
    const float* __restrict__ ag_a, const float* __restrict__ abt_a,
    const float* __restrict__ am_a, const float* __restrict__ av_a,
    const float* __restrict__ ag_b, const float* __restrict__ abt_b,
    const float* __restrict__ am_b, const float* __restrict__ av_b)
{
    __shared__ __align__(16) float xs[ICC*10*66];   // 8 ic x (8+2) rows x (64+2) cols
    __shared__ __align__(16) float ws[ICC*9*16];    // [ic*9+tap][16 oc]

    const int tid    = threadIdx.x;
    const int bz     = blockIdx.z;
    const int y_base = blockIdx.y * T1H;
    const int x_base = blockIdx.x * T1W;
    const int r0 = tid >> 6;          // 0..3
    const int c  = tid & 63;          // 0..63
    const int y0 = y_base + r0;
    const int y1 = y0 + 4;
    const int gx = x_base + c;

    float attA0 = 0.f, attA1 = 0.f, attB0 = 0.f, attB1 = 0.f;

    for (int occ = 0; occ < 8; ++occ) {
        u64 a0[8], a1[8];                 // oc pair j -> oc (occ*16 + 2j, +2j+1)
        #pragma unroll
        for (int j = 0; j < 8; ++j) { a0[j] = 0ull; a1[j] = 0ull; }

        for (int icc = 0; icc < CIN/ICC; ++icc) {
            __syncthreads();
            // stage x slab (8 ic, halo-1)
            for (int i = tid; i < ICC*10*66; i += 256) {
                int ic  = i / 660;
                int rem = i - ic*660;
                int row = rem / 66;
                int col = rem - row*66;
                int gy  = y_base + row - 1;
                int gxx = x_base + col - 1;
                float v = 0.f;
                if ((unsigned)gy < HH && (unsigned)gxx < WW)
                    v = x[(((size_t)bz*CIN + icc*ICC + ic)*HH + gy)*WW + gxx];
                xs[i] = v;
            }
            // stage weights: layout [ic*9+tap][16 oc]
            for (int i = tid; i < ICC*9*16; i += 256) {
                int kt  = i >> 4;
                int oc  = i & 15;
                int ic  = kt / 9;
                int tap = kt - ic*9;
                int ocg = occ*16 + oc;
                const float* wbase = (ocg < 64) ? (wa + (size_t)ocg*CIN*9)
                                                : (wb + (size_t)(ocg-64)*CIN*9);
                ws[i] = wbase[(icc*ICC + ic)*9 + tap];
            }
            __syncthreads();

            #pragma unroll 1
            for (int ic = 0; ic < ICC; ++ic) {
                const float* xb0 = &xs[ic*660 + r0*66 + c];
                const float* xb1 = xb0 + 4*66;
                // one ws row (16 floats) = 8 u64 pairs => row base ic*9*16, tap row = +tap*16 floats
                const u64* wrow = reinterpret_cast<const u64*>(&ws[ic*9*16]);
                #pragma unroll
                for (int tap = 0; tap < 9; ++tap) {
                    const int dy = tap/3, dx = tap - (tap/3)*3;
                    u64 X0 = pack2(xb0[dy*66 + dx]);
                    u64 X1 = pack2(xb1[dy*66 + dx]);
                    const u64* wp = wrow + tap*8;   // 8 oc-pairs for this tap
                    ffma2(a0[0], X0, wp[0]); ffma2(a1[0], X1, wp[0]);
                    ffma2(a0[1], X0, wp[1]); ffma2(a1[1], X1, wp[1]);
                    ffma2(a0[2], X0, wp[2]); ffma2(a1[2], X1, wp[2]);
                    ffma2(a0[3], X0, wp[3]); ffma2(a1[3], X1, wp[3]);
                    ffma2(a0[4], X0, wp[4]); ffma2(a1[4], X1, wp[4]);
                    ffma2(a0[5], X0, wp[5]); ffma2(a1[5], X1, wp[5]);
                    ffma2(a0[6], X0, wp[6]); ffma2(a1[6], X1, wp[6]);
                    ffma2(a0[7], X0, wp[7]); ffma2(a1[7], X1, wp[7]);
                }
            }
        }

        // epilogue: BN fold, store f, accumulate attention dot
        #pragma unroll
        for (int j = 0; j < 8; ++j) {
            float2 A0 = unpack2(a0[j]);
            float2 A1 = unpack2(a1[j]);
            #pragma unroll
            for (int h = 0; h < 2; ++h) {
                int ocg = occ*16 + j*2 + h;
                float acc0 = h ? A0.y : A0.x;
                float acc1 = h ? A1.y : A1.x;
                float s, t, wv;
                if (ocg < 64) {
                    s  = ga[ocg] * rsqrtf(va[ocg] + EPS_BR);
                    t  = (ba[ocg] - ma[ocg]) * s + bta[ocg];
                    wv = aw_a[ocg];
                } else {
                    int o2 = ocg - 64;
                    s  = gb[o2] * rsqrtf(vb[o2] + EPS_BR);
                    t  = (bb[o2] - mb[o2]) * s + btb[o2];
                    wv = aw_b[o2];
                }
                float f0 = fmaf(acc0, s, t);
                float f1 = fmaf(acc1, s, t);
                size_t fb = ((size_t)bz*OCH + ocg) * HH;
                g_fbuf[(fb + y0)*WW + gx] = f0;
                g_fbuf[(fb + y1)*WW + gx] = f1;
                if (ocg < 64) { attA0 = fmaf(wv, f0, attA0); attA1 = fmaf(wv, f1, attA1); }
                else          { attB0 = fmaf(wv, f0, attB0); attB1 = fmaf(wv, f1, attB1); }
            }
        }
    }

    // attention logit epilogue
    float ghv0 = pos_g(y0), ghv1 = pos_g(y1), gwv = pos_g(gx);

    float sA = ag_a[0] * rsqrtf(av_a[0] + EPS_ATT);
    float sB = ag_b[0] * rsqrtf(av_b[0] + EPS_ATT);

    float zA0 = attA0 + aw_a[64]*ghv0 + aw_a[65]*gwv + ab_a[0];
    float zA1 = attA1 + aw_a[64]*ghv1 + aw_a[65]*gwv + ab_a[0];
    float zB0 = attB0 + aw_b[64]*ghv0 + aw_b[65]*gwv + ab_b[0];
    float zB1 = attB1 + aw_b[64]*ghv1 + aw_b[65]*gwv + ab_b[0];

    zA0 = (zA0 - am_a[0])*sA + abt_a[0];
    zA1 = (zA1 - am_a[0])*sA + abt_a[0];
    zB0 = (zB0 - am_b[0])*sB + abt_b[0];
    zB1 = (zB1 - am_b[0])*sB + abt_b[0];

    size_t pa = ((size_t)bz*HH + y0)*WW + gx;
    size_t pb = ((size_t)bz*HH + y1)*WW + gx;
    g_att[pa] = zA0;
    g_att[pb] = zA1;
    g_att[(size_t)BATCH*HWSZ + pa] = zB0;
    g_att[(size_t)BATCH*HWSZ + pb] = zB1;
}

// ---------------------------------------------------------------------------
// Kernel 2: 3x3 attention conv + sigmoid, then out = f * (map * scale).
// Phase 1: each thread computes one map pair -> smem.
// Phase 2: (row, x-quad, 32-ch) slots do LDG.128 / 4 FMUL / STG.128.
// ---------------------------------------------------------------------------
__global__ __launch_bounds__(256)
void map_out_kernel(const float* __restrict__ awA, const float* __restrict__ awB,
                    const float* __restrict__ s1p, const float* __restrict__ s2p,
                    float* __restrict__ out)
{
    __shared__ float aA[10*34], aB[10*34];
    __shared__ float wA[36], wB[36];
    __shared__ __align__(16) float mAs[8*32], mBs[8*32];

    const int tid    = threadIdx.x;
    const int bz     = blockIdx.z;
    const int y_base = blockIdx.y * 8;
    const int x_base = blockIdx.x * 32;

    if (tid < 36) { wA[tid] = awA[tid]; wB[tid] = awB[tid]; }

    for (int i = tid; i < 340; i += 256) {
        int row = i / 34, col = i - row*34;
        int gy = y_base + row - 1, gxx = x_base + col - 1;
        float vA = 0.f, vB = 0.f;
        if ((unsigned)gy < HH && (unsigned)gxx < WW) {
            size_t idx = ((size_t)bz*HH + gy)*WW + gxx;
            vA = g_att[idx];
            vB = g_att[(size_t)BATCH*HWSZ + idx];
        }
        aA[i] = vA; aB[i] = vB;
    }
    __syncthreads();

    {
        const int ty = tid >> 5, tx = tid & 31;
        const int y = y_base + ty, x0 = x_base + tx;

        const float ghmax = 127.5f/128.f, ghmin = 0.5f/128.f;
        const float prmax = sqrtf(2.f)*ghmax, prmin = sqrtf(2.f)*ghmin;
        const float kk = 2.f/(prmax - prmin);
        const float c0 = 1.f - prmax*kk;

        float sumA = 0.f, sumB = 0.f;
        #pragma unroll
        for (int ky = 0; ky < 3; ++ky) {
            #pragma unroll
            for (int kx = 0; kx < 3; ++kx) {
                int tap = ky*3 + kx;
                int yy = y + ky - 1, xx = x0 + kx - 1;
                float av = aA[(ty+ky)*34 + tx + kx];
                float bv = aB[(ty+ky)*34 + tx + kx];
                sumA = fmaf(wA[tap], av, sumA);
                sumB = fmaf(wB[tap], bv, sumB);
                if ((unsigned)yy < HH && (unsigned)xx < WW) {
                    float ghv = pos_g(yy), gwv = pos_g(xx);
                    float prv = fmaf(kk, sqrtf(ghv*ghv + gwv*gwv), c0);
                    sumA += wA[9+tap]*ghv + wA[18+tap]*gwv + wA[27+tap]*prv;
                    sumB += wB[9+tap]*ghv + wB[18+tap]*gwv + wB[27+tap]*prv;
                }
            }
        }
        mAs[tid] = (1.f/(1.f + expf(-sumA))) * s1p[0];
        mBs[tid] = (1.f/(1.f + expf(-sumB))) * s2p[0];
    }
    __syncthreads();

    // Phase 2: 64 (row, quad) slots x 4 channel-groups of 32
    const int slot = tid & 63;
    const int cg   = tid >> 6;           // 0..3
    const int r    = slot >> 3;          // 0..7
    const int q    = slot & 7;           // 0..7

    float4 m4 = (cg < 2) ? *reinterpret_cast<float4*>(&mAs[r*32 + q*4])
                         : *reinterpret_cast<float4*>(&mBs[r*32 + q*4]);

    size_t base = (((size_t)bz*OCH + cg*32)*HH + (y_base + r))*WW + x_base + q*4;
    #pragma unroll 4
    for (int ocl = 0; ocl < 32; ++ocl) {
        size_t idx = base + (size_t)ocl*HWSZ;
        float4 f = *reinterpret_cast<const float4*>(&g_fbuf[idx]);
        f.x *= m4.x; f.y *= m4.y; f.z *= m4.z; f.w *= m4.w;
        *reinterpret_cast<float4*>(&out[idx]) = f;
    }
}

// ---------------------------------------------------------------------------
extern "C" void kernel_launch(void* const* d_in, const int* in_sizes, int n_in,
                              void* d_out, int out_size)
{
    const float* x     = (const float*)d_in[0];
    const float* wa    = (const float*)d_in[1];
    const float* ba    = (const float*)d_in[2];
    const float* wb    = (const float*)d_in[3];
    const float* bb    = (const float*)d_in[4];
    const float* ga    = (const float*)d_in[5];
    const float* bta   = (const float*)d_in[6];
    const float* ma    = (const float*)d_in[7];
    const float* va    = (const float*)d_in[8];
    const float* gb    = (const float*)d_in[9];
    const float* btb   = (const float*)d_in[10];
    const float* mb    = (const float*)d_in[11];
    const float* vb    = (const float*)d_in[12];
    const float* aw_a  = (const float*)d_in[13];
    const float* ab_a  = (const float*)d_in[14];
    const float* aw_b  = (const float*)d_in[15];
    const float* ab_b  = (const float*)d_in[16];
    const float* ag_a  = (const float*)d_in[17];
    const float* abt_a = (const float*)d_in[18];
    const float* am_a  = (const float*)d_in[19];
    const float* av_a  = (const float*)d_in[20];
    const float* ag_b  = (const float*)d_in[21];
    const float* abt_b = (const float*)d_in[22];
    const float* am_b  = (const float*)d_in[23];
    const float* av_b  = (const float*)d_in[24];
    const float* awnA  = (const float*)d_in[25];
    const float* awnB  = (const float*)d_in[26];
    const float* s1    = (const float*)d_in[27];
    const float* s2    = (const float*)d_in[28];
    float* out = (float*)d_out;

    dim3 g1(WW/T1W, HH/T1H, BATCH);   // (4, 32, 4)
    conv_bn_att_kernel<<<g1, 256>>>(x, wa, ba, wb, bb,
                                    ga, bta, ma, va, gb, btb, mb, vb,
                                    aw_a, ab_a, aw_b, ab_b,
                                    ag_a, abt_a, am_a, av_a,
                                    ag_b, abt_b, am_b, av_b);

    dim3 g2(WW/32, HH/8, BATCH);      // (8, 32, 4)
    map_out_kernel<<<g2, 256>>>(awnA, awnB, s1, s2, out);
}

// round 6
// speedup vs baseline: 1.7915x; 1.7269x over previous
#include <cuda_runtime.h>
#include <cuda_bf16.h>
#include <math.h>
#include <stdint.h>

#define BATCH 4
#define CIN   128
#define OCH   128
#define HH    256
#define WW    256
#define HWSZ  (HH*WW)

#define EPS_BR  1e-3f
#define EPS_ATT 1e-5f

typedef unsigned int u32;

#define APAD 20      // A smem row stride in u32 (16 kp + 4 pad)
#define BPAD 136     // B smem row stride in u32 (128 oc + 8 pad)

// ---------------- device scratch (allocation-free) -------------------------
// fbuf tiled: [bz][tile(512)][oc(128)][px(128)]
__device__ float g_fbuf[(size_t)BATCH*512*128*128];
__device__ float g_att[(size_t)2*BATCH*HWSZ];          // att logits: plane A, plane B
__device__ u32   g_bpre[36*2*16*BPAD];                 // [kb][hi/lo][kp][BPAD] packed bf16 pairs
__device__ float g_tvec[128];                          // folded BN offset per oc
__device__ float g_wv[128];                            // 1x1 att weight per oc

__device__ __forceinline__ float pos_g(int i) {
    return fabsf((float)i - 127.5f) * (1.0f/128.0f);
}

// pack two floats to bf16x2: low 16 = f0, high 16 = f1
__device__ __forceinline__ u32 bf16pair(float f0, float f1) {
    u32 r;
    asm("cvt.rn.bf16x2.f32 %0, %1, %2;" : "=r"(r) : "f"(f1), "f"(f0));
    return r;
}

#define MMA(c, a, b) \
    asm volatile("mma.sync.aligned.m16n8k16.row.col.f32.bf16.bf16.f32 " \
                 "{%0,%1,%2,%3}, {%4,%5,%6,%7}, {%8,%9}, {%0,%1,%2,%3};" \
                 : "+f"((c)[0]), "+f"((c)[1]), "+f"((c)[2]), "+f"((c)[3]) \
                 : "r"((a)[0]), "r"((a)[1]), "r"((a)[2]), "r"((a)[3]), \
                   "r"((b)[0]), "r"((b)[1]))

// ---------------------------------------------------------------------------
// Prepass: fold BN scale into weights, bf16 hi/lo split, pack k-pair-major:
// word[kb][h][kp][oc] = bf16x2( w[oc][ic=icc*32+2kp]*s , w[oc][ic+1]*s ).
// Also builds g_tvec (BN offset) and g_wv (1x1 att weights).
// ---------------------------------------------------------------------------
__global__ __launch_bounds__(256)
void prepass_kernel(
    const float* __restrict__ wa, const float* __restrict__ ba,
    const float* __restrict__ wb, const float* __restrict__ bb,
    const float* __restrict__ ga, const float* __restrict__ bta,
    const float* __restrict__ ma, const float* __restrict__ va,
    const float* __restrict__ gb, const float* __restrict__ btb,
    const float* __restrict__ mb, const float* __restrict__ vb,
    const float* __restrict__ aw_a, const float* __restrict__ aw_b)
{
    int gid = blockIdx.x * 256 + threadIdx.x;

    if (gid < 128) {
        float s, t;
        if (gid < 64) {
            s = ga[gid] * rsqrtf(va[gid] + EPS_BR);
            t = (ba[gid] - ma[gid]) * s + bta[gid];
            g_wv[gid] = aw_a[gid];
        } else {
            int o2 = gid - 64;
            s = gb[o2] * rsqrtf(vb[o2] + EPS_BR);
            t = (bb[o2] - mb[o2]) * s + btb[o2];
            g_wv[gid] = aw_b[o2];
        }
        g_tvec[gid] = t;
    }

    if (gid >= 36*16*128) return;
    int kb = gid >> 11;           // 0..35
    int r  = gid & 2047;
    int kp = r >> 7;              // 0..15
    int oc = r & 127;
    int icc = kb / 9, tap = kb - icc*9;
    int ic  = icc*32 + 2*kp;

    float s, w0, w1;
    if (oc < 64) {
        s = ga[oc] * rsqrtf(va[oc] + EPS_BR);
        const float* wp = wa + ((size_t)oc*CIN + ic)*9 + tap;
        w0 = wp[0]*s; w1 = wp[9]*s;
    } else {
        int o2 = oc - 64;
        s = gb[o2] * rsqrtf(vb[o2] + EPS_BR);
        const float* wp = wb + ((size_t)o2*CIN + ic)*9 + tap;
        w0 = wp[0]*s; w1 = wp[9]*s;
    }
    u32 hp = bf16pair(w0, w1);
    float h0 = __uint_as_float(hp << 16);
    float h1 = __uint_as_float(hp & 0xFFFF0000u);
    u32 lp = bf16pair(w0 - h0, w1 - h1);

    g_bpre[((kb*2 + 0)*16 + kp)*BPAD + oc] = hp;
    g_bpre[((kb*2 + 1)*16 + kp)*BPAD + oc] = lp;
}

// ---------------------------------------------------------------------------
// Conv via mma.sync bf16 (3-product hi/lo split), M=128 px, N=128 oc, K=1152.
// 8 warps: warp w -> rows (w&3)*32 px, cols (w>>2)*64 oc.
// Epilogue: +BN offset, tiled f store, 1x1 att dot (+pos terms, att-BN).
// ---------------------------------------------------------------------------
__global__ __launch_bounds__(256, 1)
void conv_mma_kernel(
    const float* __restrict__ x,
    const float* __restrict__ aw_a, const float* __restrict__ ab_a,
    const float* __restrict__ aw_b, const float* __restrict__ ab_b,
    const float* __restrict__ ag_a, const float* __restrict__ abt_a,
    const float* __restrict__ am_a, const float* __restrict__ av_a,
    const float* __restrict__ ag_b, const float* __restrict__ abt_b,
    const float* __restrict__ am_b, const float* __restrict__ av_b)
{
    __shared__ __align__(16) u32 sAh[128*APAD];
    __shared__ __align__(16) u32 sAl[128*APAD];
    __shared__ __align__(16) u32 sBh[16*BPAD];
    __shared__ __align__(16) u32 sBl[16*BPAD];

    const int tid = threadIdx.x;
    const int wid = tid >> 5, lid = tid & 31;
    const int g   = lid >> 2, tg = lid & 3;
    const int bz  = blockIdx.z;
    const int pxb = blockIdx.x * 16;
    const int pyb = blockIdx.y * 8;
    const int wm  = (wid & 3) * 32;       // pixel base for this warp
    const int wn  = (wid >> 2) * 64;      // oc base for this warp

    float acc[2][8][4];
    #pragma unroll
    for (int mt = 0; mt < 2; ++mt)
        #pragma unroll
        for (int nt = 0; nt < 8; ++nt)
            #pragma unroll
            for (int k = 0; k < 4; ++k) acc[mt][nt][k] = 0.f;

    #pragma unroll 1
    for (int kb = 0; kb < 36; ++kb) {
        const int icc = kb / 9, tap = kb - icc*9;
        const int dy = tap/3 - 1, dx = tap - (tap/3)*3 - 1;

        __syncthreads();   // previous iteration's fragment loads complete

        // ---- stage A: [px][kp] bf16x2 hi/lo ----
        #pragma unroll
        for (int it = 0; it < 8; ++it) {
            int i  = tid + it*256;        // 0..2047
            int px = i & 127, kp = i >> 7;
            int py = pyb + (px >> 4) + dy;
            int pxx = pxb + (px & 15) + dx;
            float f0 = 0.f, f1 = 0.f;
            if ((unsigned)py < HH && (unsigned)pxx < WW) {
                size_t base = (((size_t)bz*CIN + icc*32 + 2*kp)*HH + py)*WW + pxx;
                f0 = x[base];
                f1 = x[base + HWSZ];
            }
            u32 hp = bf16pair(f0, f1);
            float h0 = __uint_as_float(hp << 16);
            float h1 = __uint_as_float(hp & 0xFFFF0000u);
            u32 lp = bf16pair(f0 - h0, f1 - h1);
            sAh[px*APAD + kp] = hp;
            sAl[px*APAD + kp] = lp;
        }
        // ---- stage B: copy packed tiles ----
        {
            const uint4* srcH = (const uint4*)&g_bpre[(kb*2 + 0)*16*BPAD];
            const uint4* srcL = (const uint4*)&g_bpre[(kb*2 + 1)*16*BPAD];
            #pragma unroll
            for (int i = tid; i < 16*BPAD/4; i += 256) {
                ((uint4*)sBh)[i] = srcH[i];
                ((uint4*)sBl)[i] = srcL[i];
            }
        }
        __syncthreads();

        // ---- fragments + mma, two k16 steps ----
        #pragma unroll
        for (int step = 0; step < 2; ++step) {
            const int c0 = step*8 + tg;
            u32 ah[2][4], al[2][4], bh[8][2], bl[8][2];
            #pragma unroll
            for (int mt = 0; mt < 2; ++mt) {
                int r0 = (wm + mt*16 + g) * APAD;
                int r1 = r0 + 8*APAD;
                ah[mt][0] = sAh[r0 + c0];     ah[mt][1] = sAh[r1 + c0];
                ah[mt][2] = sAh[r0 + c0 + 4]; ah[mt][3] = sAh[r1 + c0 + 4];
                al[mt][0] = sAl[r0 + c0];     al[mt][1] = sAl[r1 + c0];
                al[mt][2] = sAl[r0 + c0 + 4]; al[mt][3] = sAl[r1 + c0 + 4];
            }
            #pragma unroll
            for (int nt = 0; nt < 8; ++nt) {
                int bc = wn + nt*8 + g;
                bh[nt][0] = sBh[(c0)*BPAD + bc];
                bh[nt][1] = sBh[(c0 + 4)*BPAD + bc];
                bl[nt][0] = sBl[(c0)*BPAD + bc];
                bl[nt][1] = sBl[(c0 + 4)*BPAD + bc];
            }
            #pragma unroll
            for (int mt = 0; mt < 2; ++mt)
                #pragma unroll
                for (int nt = 0; nt < 8; ++nt) {
                    MMA(acc[mt][nt], ah[mt], bh[nt]);
                    MMA(acc[mt][nt], al[mt], bh[nt]);
                    MMA(acc[mt][nt], ah[mt], bl[nt]);
                }
        }
    }

    // ---- epilogue ----
    __syncthreads();
    float* tv = (float*)sBh;        // 128 tvec + 128 wv
    if (tid < 128) { tv[tid] = g_tvec[tid]; tv[128 + tid] = g_wv[tid]; }
    __syncthreads();

    const int tile = blockIdx.y * 16 + blockIdx.x;
    const size_t fb = ((size_t)(bz*512 + tile)) * (128*128);

    #pragma unroll
    for (int mt = 0; mt < 2; ++mt) {
        float attP0 = 0.f, attP1 = 0.f;
        const int px0 = wm + mt*16 + g;
        const int px1 = px0 + 8;
        #pragma unroll
        for (int nt = 0; nt < 8; ++nt) {
            int oc0 = wn + nt*8 + 2*tg;
            float t0 = tv[oc0], t1 = tv[oc0 + 1];
            float w0 = tv[128 + oc0], w1 = tv[128 + oc0 + 1];
            float f0 = acc[mt][nt][0] + t0;
            float f1 = acc[mt][nt][1] + t1;
            float f2 = acc[mt][nt][2] + t0;
            float f3 = acc[mt][nt][3] + t1;
            g_fbuf[fb + (size_t)oc0*128 + px0]       = f0;
            g_fbuf[fb + (size_t)(oc0 + 1)*128 + px0] = f1;
            g_fbuf[fb + (size_t)oc0*128 + px1]       = f2;
            g_fbuf[fb + (size_t)(oc0 + 1)*128 + px1] = f3;
            attP0 = fmaf(w0, f0, fmaf(w1, f1, attP0));
            attP1 = fmaf(w0, f2, fmaf(w1, f3, attP1));
        }
        attP0 += __shfl_xor_sync(0xffffffffu, attP0, 1);
        attP0 += __shfl_xor_sync(0xffffffffu, attP0, 2);
        attP1 += __shfl_xor_sync(0xffffffffu, attP1, 1);
        attP1 += __shfl_xor_sync(0xffffffffu, attP1, 2);

        if (tg == 0) {
            #pragma unroll
            for (int hh = 0; hh < 2; ++hh) {
                int px = hh ? px1 : px0;
                float att = hh ? attP1 : attP0;
                int py = pyb + (px >> 4);
                int pxx = pxb + (px & 15);
                float ghv = pos_g(py), gwv = pos_g(pxx);
                size_t sp = (size_t)py * WW + pxx;
                if (wn == 0) {
                    float z = att + aw_a[64]*ghv + aw_a[65]*gwv + ab_a[0];
                    z = (z - am_a[0]) * (ag_a[0] * rsqrtf(av_a[0] + EPS_ATT)) + abt_a[0];
                    g_att[(size_t)bz*HWSZ + sp] = z;
                } else {
                    float z = att + aw_b[64]*ghv + aw_b[65]*gwv + ab_b[0];
                    z = (z - am_b[0]) * (ag_b[0] * rsqrtf(av_b[0] + EPS_ATT)) + abt_b[0];
                    g_att[(size_t)BATCH*HWSZ + (size_t)bz*HWSZ + sp] = z;
                }
            }
        }
    }
}

// ---------------------------------------------------------------------------
// Kernel 2: 3x3 attention conv over [att, gh, gw, pr] + sigmoid, then
// out = f * (map * scale). Reads tiled fbuf, writes NCHW out.
// ---------------------------------------------------------------------------
__global__ __launch_bounds__(256)
void map_out_kernel(const float* __restrict__ awA, const float* __restrict__ awB,
                    const float* __restrict__ s1p, const float* __restrict__ s2p,
                    float* __restrict__ out)
{
    __shared__ float aA[10*34], aB[10*34];
    __shared__ float wA[36], wB[36];
    __shared__ __align__(16) float mAs[8*32], mBs[8*32];

    const int tid    = threadIdx.x;
    const int bz     = blockIdx.z;
    const int y_base = blockIdx.y * 8;
    const int x_base = blockIdx.x * 32;

    if (tid < 36) { wA[tid] = awA[tid]; wB[tid] = awB[tid]; }

    for (int i = tid; i < 340; i += 256) {
        int row = i / 34, col = i - row*34;
        int gy = y_base + row - 1, gxx = x_base + col - 1;
        float vA = 0.f, vB = 0.f;
        if ((unsigned)gy < HH && (unsigned)gxx < WW) {
            size_t idx = ((size_t)bz*HH + gy)*WW + gxx;
            vA = g_att[idx];
            vB = g_att[(size_t)BATCH*HWSZ + idx];
        }
        aA[i] = vA; aB[i] = vB;
    }
    __syncthreads();

    {
        const int ty = tid >> 5, tx = tid & 31;
        const int y = y_base + ty, x0 = x_base + tx;

        const float ghmax = 127.5f/128.f, ghmin = 0.5f/128.f;
        const float prmax = sqrtf(2.f)*ghmax, prmin = sqrtf(2.f)*ghmin;
        const float kk = 2.f/(prmax - prmin);
        const float c0 = 1.f - prmax*kk;

        float sumA = 0.f, sumB = 0.f;
        #pragma unroll
        for (int ky = 0; ky < 3; ++ky) {
            #pragma unroll
            for (int kx = 0; kx < 3; ++kx) {
                int tap = ky*3 + kx;
                int yy = y + ky - 1, xx = x0 + kx - 1;
                float av = aA[(ty+ky)*34 + tx + kx];
                float bv = aB[(ty+ky)*34 + tx + kx];
                sumA = fmaf(wA[tap], av, sumA);
                sumB = fmaf(wB[tap], bv, sumB);
                if ((unsigned)yy < HH && (unsigned)xx < WW) {
                    float ghv = pos_g(yy), gwv = pos_g(xx);
                    float prv = fmaf(kk, sqrtf(ghv*ghv + gwv*gwv), c0);
                    sumA += wA[9+tap]*ghv + wA[18+tap]*gwv + wA[27+tap]*prv;
                    sumB += wB[9+tap]*ghv + wB[18+tap]*gwv + wB[27+tap]*prv;
                }
            }
        }
        mAs[tid] = (1.f/(1.f + expf(-sumA))) * s1p[0];
        mBs[tid] = (1.f/(1.f + expf(-sumB))) * s2p[0];
    }
    __syncthreads();

    const int slot = tid & 63;
    const int cg   = tid >> 6;        // 0..3 (channel groups of 32)
    const int r    = slot >> 3;       // row 0..7
    const int q    = slot & 7;        // x quad 0..7

    float4 m4 = (cg < 2) ? *reinterpret_cast<float4*>(&mAs[r*32 + q*4])
                         : *reinterpret_cast<float4*>(&mBs[r*32 + q*4]);

    const int y  = y_base + r;
    const int xx = x_base + q*4;
    const int tile = (y >> 3)*16 + (xx >> 4);
    const int pxIn = (y & 7)*16 + (xx & 15);
    size_t fidx = ((size_t)(bz*512 + tile))*(128*128) + (size_t)(cg*32)*128 + pxIn;
    size_t oidx = (((size_t)bz*OCH + cg*32)*HH + y)*WW + xx;

    #pragma unroll 4
    for (int ocl = 0; ocl < 32; ++ocl) {
        float4 f = *reinterpret_cast<const float4*>(&g_fbuf[fidx + (size_t)ocl*128]);
        f.x *= m4.x; f.y *= m4.y; f.z *= m4.z; f.w *= m4.w;
        *reinterpret_cast<float4*>(&out[oidx + (size_t)ocl*HWSZ]) = f;
    }
}

// ---------------------------------------------------------------------------
extern "C" void kernel_launch(void* const* d_in, const int* in_sizes, int n_in,
                              void* d_out, int out_size)
{
    const float* x     = (const float*)d_in[0];
    const float* wa    = (const float*)d_in[1];
    const float* ba    = (const float*)d_in[2];
    const float* wb    = (const float*)d_in[3];
    const float* bb    = (const float*)d_in[4];
    const float* ga    = (const float*)d_in[5];
    const float* bta   = (const float*)d_in[6];
    const float* ma    = (const float*)d_in[7];
    const float* va    = (const float*)d_in[8];
    const float* gb    = (const float*)d_in[9];
    const float* btb   = (const float*)d_in[10];
    const float* mb    = (const float*)d_in[11];
    const float* vb    = (const float*)d_in[12];
    const float* aw_a  = (const float*)d_in[13];
    const float* ab_a  = (const float*)d_in[14];
    const float* aw_b  = (const float*)d_in[15];
    const float* ab_b  = (const float*)d_in[16];
    const float* ag_a  = (const float*)d_in[17];
    const float* abt_a = (const float*)d_in[18];
    const float* am_a  = (const float*)d_in[19];
    const float* av_a  = (const float*)d_in[20];
    const float* ag_b  = (const float*)d_in[21];
    const float* abt_b = (const float*)d_in[22];
    const float* am_b  = (const float*)d_in[23];
    const float* av_b  = (const float*)d_in[24];
    const float* awnA  = (const float*)d_in[25];
    const float* awnB  = (const float*)d_in[26];
    const float* s1    = (const float*)d_in[27];
    const float* s2    = (const float*)d_in[28];
    float* out = (float*)d_out;

    prepass_kernel<<<288, 256>>>(wa, ba, wb, bb, ga, bta, ma, va,
                                 gb, btb, mb, vb, aw_a, aw_b);

    dim3 g1(WW/16, HH/8, BATCH);      // (16, 32, 4) = 2048 CTAs
    conv_mma_kernel<<<g1, 256>>>(x,
                                 aw_a, ab_a, aw_b, ab_b,
                                 ag_a, abt_a, am_a, av_a,
                                 ag_b, abt_b, am_b, av_b);

    dim3 g2(WW/32, HH/8, BATCH);      // (8, 32, 4)
    map_out_kernel<<<g2, 256>>>(awnA, awnB, s1, s2, out);
}